// round 1
// baseline (speedup 1.0000x reference)
#include <cuda_runtime.h>
#include <math.h>

// Problem constants
#define B_ 8
#define M_ 2048
#define IN_ 512
#define H_ 8
#define D_ 64
#define HD_ 512   // H_*D_

// Scratch (allocation-free rule: __device__ globals)
__device__ float g_Q[(size_t)B_ * M_ * HD_];
__device__ float g_K[(size_t)B_ * M_ * HD_];
__device__ float g_V[(size_t)B_ * M_ * HD_];
__device__ float g_C[(size_t)B_ * M_ * HD_];

// ---------------------------------------------------------------------------
// Tiled fp32 GEMM: C[M,N] = A[M,K] @ W[K,N] (+ bias). 64x64 tile, BK=16,
// 256 threads, 4x4 register blocking.
// ---------------------------------------------------------------------------
template <bool HAS_BIAS>
__global__ void __launch_bounds__(256) gemm64(
    const float* __restrict__ A, const float* __restrict__ W,
    const float* __restrict__ bias, float* __restrict__ C,
    int Mdim, int Ndim, int Kdim)
{
    __shared__ float As[16][65];  // [k][m], padded -> conflict-free transp. store
    __shared__ float Bs[16][64];  // [k][n]

    const int tid = threadIdx.x;
    const int tx = tid & 15, ty = tid >> 4;
    const int m0 = blockIdx.y * 64, n0 = blockIdx.x * 64;

    const int arow = tid >> 2, acol = (tid & 3) * 4;   // A tile: 64 rows x 16 cols
    const int brow = tid >> 4, bcol = (tid & 15) * 4;  // B tile: 16 rows x 64 cols

    float acc[4][4] = {};

    for (int k0 = 0; k0 < Kdim; k0 += 16) {
        float4 av = *(const float4*)(A + (size_t)(m0 + arow) * Kdim + k0 + acol);
        float4 bv = *(const float4*)(W + (size_t)(k0 + brow) * Ndim + n0 + bcol);
        As[acol + 0][arow] = av.x;
        As[acol + 1][arow] = av.y;
        As[acol + 2][arow] = av.z;
        As[acol + 3][arow] = av.w;
        *(float4*)&Bs[brow][bcol] = bv;
        __syncthreads();

#pragma unroll
        for (int kk = 0; kk < 16; kk++) {
            float a0 = As[kk][ty * 4 + 0];
            float a1 = As[kk][ty * 4 + 1];
            float a2 = As[kk][ty * 4 + 2];
            float a3 = As[kk][ty * 4 + 3];
            float4 b = *(const float4*)&Bs[kk][tx * 4];
            acc[0][0] += a0 * b.x; acc[0][1] += a0 * b.y; acc[0][2] += a0 * b.z; acc[0][3] += a0 * b.w;
            acc[1][0] += a1 * b.x; acc[1][1] += a1 * b.y; acc[1][2] += a1 * b.z; acc[1][3] += a1 * b.w;
            acc[2][0] += a2 * b.x; acc[2][1] += a2 * b.y; acc[2][2] += a2 * b.z; acc[2][3] += a2 * b.w;
            acc[3][0] += a3 * b.x; acc[3][1] += a3 * b.y; acc[3][2] += a3 * b.z; acc[3][3] += a3 * b.w;
        }
        __syncthreads();
    }

#pragma unroll
    for (int i = 0; i < 4; i++) {
        int m = m0 + ty * 4 + i;
        int n = n0 + tx * 4;
        float4 r;
        r.x = acc[i][0]; r.y = acc[i][1]; r.z = acc[i][2]; r.w = acc[i][3];
        if (HAS_BIAS) {
            r.x += bias[n + 0]; r.y += bias[n + 1];
            r.z += bias[n + 2]; r.w += bias[n + 3];
        }
        *(float4*)&C[(size_t)m * Ndim + n] = r;
    }
}

// ---------------------------------------------------------------------------
// Flash attention, fp32 CUDA cores.
// CTA = (b, h, 64-query tile). 8 warps x 8 query rows. 64-key tiles.
// Lane owns keys {lane, lane+32} for S, dims {lane, lane+32} for O.
// logits multiplied by sqrt(512) per the reference (divide by HEAD_DIM**-0.5).
// ---------------------------------------------------------------------------
__global__ void __launch_bounds__(256) attn64(
    const float* __restrict__ Q, const float* __restrict__ K,
    const float* __restrict__ V, float* __restrict__ O)
{
    extern __shared__ float sm[];
    float (*Qs)[65] = (float(*)[65])(sm);
    float (*Ks)[65] = (float(*)[65])(sm + 64 * 65);
    float (*Vs)[65] = (float(*)[65])(sm + 2 * 64 * 65);
    float (*Ps)[65] = (float(*)[65])(sm + 3 * 64 * 65);

    const int tid  = threadIdx.x;
    const int lane = tid & 31, warp = tid >> 5;
    const int bh   = blockIdx.y;
    const int b    = bh >> 3, h = bh & 7;
    const int q0   = blockIdx.x * 64;
    const size_t base = (size_t)b * M_ * HD_ + (size_t)h * D_;  // + m*HD_ + d

    // Load Q tile (64 rows x 64 dims)
#pragma unroll
    for (int p = 0; p < 4; p++) {
        int row = p * 16 + (tid >> 4);
        int c4  = (tid & 15) * 4;
        float4 v = *(const float4*)(Q + base + (size_t)(q0 + row) * HD_ + c4);
        Qs[row][c4 + 0] = v.x; Qs[row][c4 + 1] = v.y;
        Qs[row][c4 + 2] = v.z; Qs[row][c4 + 3] = v.w;
    }

    float o0[8] = {}, o1[8] = {};
    float mrow[8], lrow[8];
#pragma unroll
    for (int r = 0; r < 8; r++) { mrow[r] = -INFINITY; lrow[r] = 0.0f; }

    const int r0 = warp * 8;
    const float scale = 22.62741699796952f;  // sqrt(512)

    for (int kt = 0; kt < M_ / 64; kt++) {
        __syncthreads();
        // Load K,V tiles
#pragma unroll
        for (int p = 0; p < 4; p++) {
            int row = p * 16 + (tid >> 4);
            int c4  = (tid & 15) * 4;
            const size_t g = base + (size_t)(kt * 64 + row) * HD_ + c4;
            float4 kv = *(const float4*)(K + g);
            float4 vv = *(const float4*)(V + g);
            Ks[row][c4 + 0] = kv.x; Ks[row][c4 + 1] = kv.y;
            Ks[row][c4 + 2] = kv.z; Ks[row][c4 + 3] = kv.w;
            Vs[row][c4 + 0] = vv.x; Vs[row][c4 + 1] = vv.y;
            Vs[row][c4 + 2] = vv.z; Vs[row][c4 + 3] = vv.w;
        }
        __syncthreads();

        // S = Q K^T  (per-warp rows r0..r0+7, lane keys lane & lane+32)
        float s0[8] = {}, s1[8] = {};
#pragma unroll 4
        for (int d = 0; d < 64; d++) {
            float k0v = Ks[lane][d];
            float k1v = Ks[lane + 32][d];
#pragma unroll
            for (int r = 0; r < 8; r++) {
                float qv = Qs[r0 + r][d];
                s0[r] += qv * k0v;
                s1[r] += qv * k1v;
            }
        }

        // Online softmax per row
#pragma unroll
        for (int r = 0; r < 8; r++) {
            float v0 = s0[r] * scale, v1 = s1[r] * scale;
            float tmax = fmaxf(v0, v1);
#pragma unroll
            for (int off = 16; off > 0; off >>= 1)
                tmax = fmaxf(tmax, __shfl_xor_sync(0xffffffffu, tmax, off));
            float mnew = fmaxf(mrow[r], tmax);
            float p0 = __expf(v0 - mnew);
            float p1 = __expf(v1 - mnew);
            float psum = p0 + p1;
#pragma unroll
            for (int off = 16; off > 0; off >>= 1)
                psum += __shfl_xor_sync(0xffffffffu, psum, off);
            float corr = __expf(mrow[r] - mnew);
            lrow[r] = lrow[r] * corr + psum;
            o0[r] *= corr;
            o1[r] *= corr;
            mrow[r] = mnew;
            Ps[r0 + r][lane]      = p0;
            Ps[r0 + r][lane + 32] = p1;
        }
        __syncwarp();

        // O += P V (lane owns dims lane & lane+32)
#pragma unroll 4
        for (int k = 0; k < 64; k++) {
            float v0 = Vs[k][lane];
            float v1 = Vs[k][lane + 32];
#pragma unroll
            for (int r = 0; r < 8; r++) {
                float pv = Ps[r0 + r][k];
                o0[r] += pv * v0;
                o1[r] += pv * v1;
            }
        }
    }

    // Normalize + write merged context [B, M, H*D]
#pragma unroll
    for (int r = 0; r < 8; r++) {
        float inv = 1.0f / lrow[r];
        size_t idx = base + (size_t)(q0 + r0 + r) * HD_;
        O[idx + lane]      = o0[r] * inv;
        O[idx + lane + 32] = o1[r] * inv;
    }
}

// ---------------------------------------------------------------------------
extern "C" void kernel_launch(void* const* d_in, const int* in_sizes, int n_in,
                              void* d_out, int out_size)
{
    const float* x  = (const float*)d_in[0];
    const float* Wq = (const float*)d_in[1];
    const float* Wk = (const float*)d_in[2];
    const float* Wv = (const float*)d_in[3];
    const float* Wo = (const float*)d_in[4];
    const float* bo = (const float*)d_in[5];
    float* out = (float*)d_out;

    float *Qp, *Kp, *Vp, *Cp;
    cudaGetSymbolAddress((void**)&Qp, g_Q);
    cudaGetSymbolAddress((void**)&Kp, g_K);
    cudaGetSymbolAddress((void**)&Vp, g_V);
    cudaGetSymbolAddress((void**)&Cp, g_C);

    const int BM = B_ * M_;  // 16384 rows

    // QKV projections
    dim3 gQKV(HD_ / 64, BM / 64);
    gemm64<false><<<gQKV, 256>>>(x, Wq, nullptr, Qp, BM, HD_, IN_);
    gemm64<false><<<gQKV, 256>>>(x, Wk, nullptr, Kp, BM, HD_, IN_);
    gemm64<false><<<gQKV, 256>>>(x, Wv, nullptr, Vp, BM, HD_, IN_);

    // Attention
    size_t smem = (size_t)4 * 64 * 65 * sizeof(float);  // 66560 B
    cudaFuncSetAttribute(attn64, cudaFuncAttributeMaxDynamicSharedMemorySize,
                         (int)smem);
    attn64<<<dim3(M_ / 64, B_ * H_), 256, smem>>>(Qp, Kp, Vp, Cp);

    // Output projection + bias
    gemm64<true><<<dim3(IN_ / 64, BM / 64), 256>>>(Cp, Wo, bo, out, BM, IN_, HD_);
}